// round 3
// baseline (speedup 1.0000x reference)
#include <cuda_runtime.h>

// Problem dims (fixed by the dataset)
#define L_DIM 131072
#define B_DIM 512
#define D_DIM 768
#define NNZ_DIM 2048

// Tiling config (shared by all three GEMMs)
#define BM 128
#define BN 128
#define BK 16
#define LDS_PAD (BM + 4)   // row stride 132 floats = 528B: 16B-aligned, <=2-way STS conflicts
#define K3_SPLITS 32
#define K3_CHUNK (L_DIM / K3_SPLITS)   // 4096

// Scratch (allocation-free mechanism: __device__ globals).
// g_buf: 256 MB for g = sigmoid(W E^T) with scatter applied.
// part_buf: 48 MB split-K partials for the gradient GEMM (deterministic reduce).
static __device__ float g_buf[(size_t)L_DIM * (size_t)B_DIM];
static __device__ float part_buf[(size_t)K3_SPLITS * B_DIM * D_DIM];

// ---------------------------------------------------------------------------
// K1: g_buf = sigmoid(W @ E^T)   [L,B] = [L,D] x [B,D]^T   (GEMM-NT)
// ---------------------------------------------------------------------------
__global__ __launch_bounds__(256)
void k1_logits_sigmoid(const float* __restrict__ W, const float* __restrict__ E) {
    __shared__ float As[BK][LDS_PAD];
    __shared__ float Bs[BK][LDS_PAD];
    const int tid = threadIdx.x;
    const int tx = tid & 15;          // output col group (N)
    const int ty = tid >> 4;          // output row group (M)
    const int m0 = blockIdx.y * BM;
    const int n0 = blockIdx.x * BN;

    float acc[8][8];
#pragma unroll
    for (int i = 0; i < 8; i++)
#pragma unroll
        for (int j = 0; j < 8; j++) acc[i][j] = 0.0f;

    for (int k0 = 0; k0 < D_DIM; k0 += BK) {
        // A: W[m0+m][k0+k..]  -> As[k][m]   (transposed stage)
        // B: E[n0+n][k0+k..]  -> Bs[k][n]   (transposed stage)
#pragma unroll
        for (int i = 0; i < 2; i++) {
            int id = tid + i * 256;      // 0..511
            int r  = id >> 2;            // 0..127 (m or n)
            int k4 = (id & 3) * 4;       // 0,4,8,12
            float4 va = *reinterpret_cast<const float4*>(
                &W[(size_t)(m0 + r) * D_DIM + k0 + k4]);
            As[k4 + 0][r] = va.x; As[k4 + 1][r] = va.y;
            As[k4 + 2][r] = va.z; As[k4 + 3][r] = va.w;
            float4 vb = *reinterpret_cast<const float4*>(
                &E[(size_t)(n0 + r) * D_DIM + k0 + k4]);
            Bs[k4 + 0][r] = vb.x; Bs[k4 + 1][r] = vb.y;
            Bs[k4 + 2][r] = vb.z; Bs[k4 + 3][r] = vb.w;
        }
        __syncthreads();
#pragma unroll
        for (int kk = 0; kk < BK; kk++) {
            float a[8], b[8];
            *reinterpret_cast<float4*>(&a[0]) = *reinterpret_cast<const float4*>(&As[kk][ty * 8]);
            *reinterpret_cast<float4*>(&a[4]) = *reinterpret_cast<const float4*>(&As[kk][ty * 8 + 4]);
            *reinterpret_cast<float4*>(&b[0]) = *reinterpret_cast<const float4*>(&Bs[kk][tx * 8]);
            *reinterpret_cast<float4*>(&b[4]) = *reinterpret_cast<const float4*>(&Bs[kk][tx * 8 + 4]);
#pragma unroll
            for (int i = 0; i < 8; i++)
#pragma unroll
                for (int j = 0; j < 8; j++)
                    acc[i][j] += a[i] * b[j];
        }
        __syncthreads();
    }

    // Epilogue: sigmoid, store to g_buf
#pragma unroll
    for (int i = 0; i < 8; i++) {
        float r[8];
#pragma unroll
        for (int j = 0; j < 8; j++)
            r[j] = 1.0f / (1.0f + __expf(-acc[i][j]));
        float* dst = &g_buf[(size_t)(m0 + ty * 8 + i) * B_DIM + n0 + tx * 8];
        *reinterpret_cast<float4*>(dst)     = *reinterpret_cast<float4*>(&r[0]);
        *reinterpret_cast<float4*>(dst + 4) = *reinterpret_cast<float4*>(&r[4]);
    }
}

// ---------------------------------------------------------------------------
// K1b: scatter  g[label_cols[i], label_rows[i]] -= 1
// atomicAdd of an identical constant is order-invariant bit-exact -> deterministic.
// ---------------------------------------------------------------------------
__global__ void k_scatter(const int* __restrict__ rows, const int* __restrict__ cols) {
    int i = blockIdx.x * blockDim.x + threadIdx.x;
    if (i < NNZ_DIM)
        atomicAdd(&g_buf[(size_t)cols[i] * B_DIM + rows[i]], -1.0f);
}

// ---------------------------------------------------------------------------
// K2: Wout = W - lr * (g @ E)   [L,D] = [L,B] x [B,D]   (GEMM-NN)
// ---------------------------------------------------------------------------
__global__ __launch_bounds__(256)
void k2_update(const float* __restrict__ W, const float* __restrict__ E,
               const float* __restrict__ lr_p, float* __restrict__ Wout) {
    __shared__ float As[BK][LDS_PAD];
    __shared__ float Bs[BK][LDS_PAD];
    const int tid = threadIdx.x;
    const int tx = tid & 15;
    const int ty = tid >> 4;
    const int m0 = blockIdx.y * BM;
    const int n0 = blockIdx.x * BN;

    float acc[8][8];
#pragma unroll
    for (int i = 0; i < 8; i++)
#pragma unroll
        for (int j = 0; j < 8; j++) acc[i][j] = 0.0f;

    for (int k0 = 0; k0 < B_DIM; k0 += BK) {
        // A: g[m0+m][k0+k..] -> As[k][m]  (transposed stage)
#pragma unroll
        for (int i = 0; i < 2; i++) {
            int id = tid + i * 256;
            int m  = id >> 2;
            int k4 = (id & 3) * 4;
            float4 va = *reinterpret_cast<const float4*>(
                &g_buf[(size_t)(m0 + m) * B_DIM + k0 + k4]);
            As[k4 + 0][m] = va.x; As[k4 + 1][m] = va.y;
            As[k4 + 2][m] = va.z; As[k4 + 3][m] = va.w;
        }
        // B: E[k0+k][n0+n..] -> Bs[k][n]  (direct stage, coalesced float4)
#pragma unroll
        for (int i = 0; i < 2; i++) {
            int id = tid + i * 256;
            int k  = id >> 5;            // 0..15
            int n4 = (id & 31) * 4;      // 0..124
            *reinterpret_cast<float4*>(&Bs[k][n4]) =
                *reinterpret_cast<const float4*>(&E[(size_t)(k0 + k) * D_DIM + n0 + n4]);
        }
        __syncthreads();
#pragma unroll
        for (int kk = 0; kk < BK; kk++) {
            float a[8], b[8];
            *reinterpret_cast<float4*>(&a[0]) = *reinterpret_cast<const float4*>(&As[kk][ty * 8]);
            *reinterpret_cast<float4*>(&a[4]) = *reinterpret_cast<const float4*>(&As[kk][ty * 8 + 4]);
            *reinterpret_cast<float4*>(&b[0]) = *reinterpret_cast<const float4*>(&Bs[kk][tx * 8]);
            *reinterpret_cast<float4*>(&b[4]) = *reinterpret_cast<const float4*>(&Bs[kk][tx * 8 + 4]);
#pragma unroll
            for (int i = 0; i < 8; i++)
#pragma unroll
                for (int j = 0; j < 8; j++)
                    acc[i][j] += a[i] * b[j];
        }
        __syncthreads();
    }

    const float lr = __ldg(lr_p);
#pragma unroll
    for (int i = 0; i < 8; i++) {
        size_t base = (size_t)(m0 + ty * 8 + i) * D_DIM + n0 + tx * 8;
        float4 w0 = *reinterpret_cast<const float4*>(&W[base]);
        float4 w1 = *reinterpret_cast<const float4*>(&W[base + 4]);
        float4 o0, o1;
        o0.x = w0.x - lr * acc[i][0]; o0.y = w0.y - lr * acc[i][1];
        o0.z = w0.z - lr * acc[i][2]; o0.w = w0.w - lr * acc[i][3];
        o1.x = w1.x - lr * acc[i][4]; o1.y = w1.y - lr * acc[i][5];
        o1.z = w1.z - lr * acc[i][6]; o1.w = w1.w - lr * acc[i][7];
        *reinterpret_cast<float4*>(&Wout[base])     = o0;
        *reinterpret_cast<float4*>(&Wout[base + 4]) = o1;
    }
}

// ---------------------------------------------------------------------------
// K3: part_buf[z] = g[z-chunk]^T @ W[z-chunk]   (GEMM-TN, split-K, no atomics)
// ---------------------------------------------------------------------------
__global__ __launch_bounds__(256)
void k3_grad_partial(const float* __restrict__ W) {
    __shared__ float As[BK][LDS_PAD];
    __shared__ float Bs[BK][LDS_PAD];
    const int tid = threadIdx.x;
    const int tx = tid & 15;
    const int ty = tid >> 4;
    const int m0 = blockIdx.y * BM;                  // over B (512)
    const int n0 = blockIdx.x * BN;                  // over D (768)
    const int z  = blockIdx.z;                       // split-K slice
    const int kbase = z * K3_CHUNK;                  // over L (131072)

    float acc[8][8];
#pragma unroll
    for (int i = 0; i < 8; i++)
#pragma unroll
        for (int j = 0; j < 8; j++) acc[i][j] = 0.0f;

    for (int k0 = kbase; k0 < kbase + K3_CHUNK; k0 += BK) {
        // A: As[k][m] = g[k0+k][m0+m]   (direct stage, coalesced)
        // B: Bs[k][n] = W[k0+k][n0+n]   (direct stage, coalesced)
#pragma unroll
        for (int i = 0; i < 2; i++) {
            int id = tid + i * 256;
            int k  = id >> 5;
            int c4 = (id & 31) * 4;
            *reinterpret_cast<float4*>(&As[k][c4]) =
                *reinterpret_cast<const float4*>(&g_buf[(size_t)(k0 + k) * B_DIM + m0 + c4]);
            *reinterpret_cast<float4*>(&Bs[k][c4]) =
                *reinterpret_cast<const float4*>(&W[(size_t)(k0 + k) * D_DIM + n0 + c4]);
        }
        __syncthreads();
#pragma unroll
        for (int kk = 0; kk < BK; kk++) {
            float a[8], b[8];
            *reinterpret_cast<float4*>(&a[0]) = *reinterpret_cast<const float4*>(&As[kk][ty * 8]);
            *reinterpret_cast<float4*>(&a[4]) = *reinterpret_cast<const float4*>(&As[kk][ty * 8 + 4]);
            *reinterpret_cast<float4*>(&b[0]) = *reinterpret_cast<const float4*>(&Bs[kk][tx * 8]);
            *reinterpret_cast<float4*>(&b[4]) = *reinterpret_cast<const float4*>(&Bs[kk][tx * 8 + 4]);
#pragma unroll
            for (int i = 0; i < 8; i++)
#pragma unroll
                for (int j = 0; j < 8; j++)
                    acc[i][j] += a[i] * b[j];
        }
        __syncthreads();
    }

    float* part = &part_buf[(size_t)z * B_DIM * D_DIM];
#pragma unroll
    for (int i = 0; i < 8; i++) {
        size_t base = (size_t)(m0 + ty * 8 + i) * D_DIM + n0 + tx * 8;
        *reinterpret_cast<float4*>(&part[base])     = *reinterpret_cast<float4*>(&acc[i][0]);
        *reinterpret_cast<float4*>(&part[base + 4]) = *reinterpret_cast<float4*>(&acc[i][4]);
    }
}

// ---------------------------------------------------------------------------
// K4: grad = sum_z part_buf[z]   (fixed order -> deterministic)
// ---------------------------------------------------------------------------
__global__ __launch_bounds__(256)
void k4_reduce(float* __restrict__ grad) {
    const int n = B_DIM * D_DIM;                 // 393216 floats = 98304 float4
    int i4 = blockIdx.x * blockDim.x + threadIdx.x;
    if (i4 * 4 >= n) return;
    float4 s = make_float4(0.f, 0.f, 0.f, 0.f);
#pragma unroll
    for (int z = 0; z < K3_SPLITS; z++) {
        float4 v = *reinterpret_cast<const float4*>(&part_buf[(size_t)z * n + i4 * 4]);
        s.x += v.x; s.y += v.y; s.z += v.z; s.w += v.w;
    }
    *reinterpret_cast<float4*>(&grad[i4 * 4]) = s;
}

// ---------------------------------------------------------------------------
// Launch. Output layout: [grad_input (B*D) | w_new (L*D)]  (reference return order)
// ---------------------------------------------------------------------------
extern "C" void kernel_launch(void* const* d_in, const int* in_sizes, int n_in,
                              void* d_out, int out_size) {
    const float* embed  = nullptr;
    const float* weight = nullptr;
    const float* lr     = nullptr;
    const int*   rows   = nullptr;
    const int*   cols   = nullptr;

    // Identify inputs by element count (robust to ordering); rows before cols
    // per setup_inputs() dict order.
    for (int i = 0; i < n_in; i++) {
        int s = in_sizes[i];
        if (s == B_DIM * D_DIM)                 embed  = (const float*)d_in[i];
        else if (s == 1)                        lr     = (const float*)d_in[i];
        else if (s == NNZ_DIM) {
            if (!rows) rows = (const int*)d_in[i];
            else       cols = (const int*)d_in[i];
        } else                                  weight = (const float*)d_in[i];
    }

    float* out  = (float*)d_out;
    float* grad = out;                                   // [B, D]
    float* wout = out + (size_t)B_DIM * D_DIM;           // [L, D]

    // 1) g = sigmoid(W E^T)
    k1_logits_sigmoid<<<dim3(B_DIM / BN, L_DIM / BM), 256>>>(weight, embed);
    // 2) scatter -1 at positives (order-invariant constant add -> deterministic)
    k_scatter<<<NNZ_DIM / 256, 256>>>(rows, cols);
    // 3) W_new = W - lr * (g @ E)
    k2_update<<<dim3(D_DIM / BN, L_DIM / BM), 256>>>(weight, embed, lr, wout);
    // 4) split-K partials of grad = g^T @ W
    k3_grad_partial<<<dim3(D_DIM / BN, B_DIM / BM, K3_SPLITS), 256>>>(weight);
    // 5) deterministic fixed-order reduction
    k4_reduce<<<(B_DIM * D_DIM / 4 + 255) / 256, 256>>>(grad);
}

// round 7
// speedup vs baseline: 1.8513x; 1.8513x over previous
#include <cuda_runtime.h>
#include <cuda_bf16.h>
#include <cstdint>

// Problem dims (fixed by the dataset)
#define L_DIM 131072
#define B_DIM 512
#define D_DIM 768
#define NNZ_DIM 2048

#define K3_SPLITS 32
#define K3_CHUNK (L_DIM / K3_SPLITS)   // 4096

// GEMM tiling (mma.sync path, plain sm_100-compatible)
#define CTA_M 128
#define CTA_N 128
#define CTA_K 32
#define STAGES 3
#define ROW_PITCH 80                     // 64B data + 16B pad -> conflict-free LDSM
#define BUF_BYTES (128 * ROW_PITCH)      // 10240 per operand-half
#define STAGE_BYTES (4 * BUF_BYTES)      // Ahi, Alo, Bhi, Blo = 40960
#define GEMM_SMEM (STAGES * STAGE_BYTES) // 122880

// ---------------------------------------------------------------------------
// Scratch (__device__ globals = allocation-free scratch)
// ---------------------------------------------------------------------------
static __device__ float          g_buf[(size_t)L_DIM * B_DIM];                 // fp32 g
static __device__ __nv_bfloat16  Whl [(size_t)2 * L_DIM * D_DIM];              // [2L, D]
static __device__ __nv_bfloat16  WThl[(size_t)2 * D_DIM * L_DIM];              // [2D, L]
static __device__ __nv_bfloat16  ghl [(size_t)2 * L_DIM * B_DIM];              // [2L, B]
static __device__ __nv_bfloat16  gThl[(size_t)2 * B_DIM * L_DIM];              // [2B, L]
static __device__ __nv_bfloat16  Ehl [(size_t)2 * B_DIM * D_DIM];              // [2B, D]
static __device__ __nv_bfloat16  EThl[(size_t)2 * D_DIM * B_DIM];              // [2D, B]
static __device__ float          part_buf[(size_t)K3_SPLITS * B_DIM * D_DIM];

// ---------------------------------------------------------------------------
// sm_80-level PTX helpers (legal on plain sm_100 target)
// ---------------------------------------------------------------------------
__device__ __forceinline__ uint32_t smem_u32(const void* p) {
    uint32_t a;
    asm("{ .reg .u64 t; cvta.to.shared.u64 t, %1; cvt.u32.u64 %0, t; }" : "=r"(a) : "l"(p));
    return a;
}
__device__ __forceinline__ void cp16(uint32_t dst, const void* src) {
    asm volatile("cp.async.cg.shared.global [%0], [%1], 16;" :: "r"(dst), "l"(src));
}
__device__ __forceinline__ void cp_commit() {
    asm volatile("cp.async.commit_group;" ::: "memory");
}
template <int N>
__device__ __forceinline__ void cp_wait() {
    asm volatile("cp.async.wait_group %0;" :: "n"(N) : "memory");
}
__device__ __forceinline__ void ldsm4(uint32_t* d, uint32_t addr) {
    asm volatile("ldmatrix.sync.aligned.m8n8.x4.shared.b16 {%0,%1,%2,%3}, [%4];"
        : "=r"(d[0]), "=r"(d[1]), "=r"(d[2]), "=r"(d[3]) : "r"(addr));
}
__device__ __forceinline__ void mma16816(float* c, const uint32_t* a, uint32_t b0, uint32_t b1) {
    asm volatile("mma.sync.aligned.m16n8k16.row.col.f32.bf16.bf16.f32 "
        "{%0,%1,%2,%3}, {%4,%5,%6,%7}, {%8,%9}, {%0,%1,%2,%3};"
        : "+f"(c[0]), "+f"(c[1]), "+f"(c[2]), "+f"(c[3])
        : "r"(a[0]), "r"(a[1]), "r"(a[2]), "r"(a[3]), "r"(b0), "r"(b1));
}

// ---------------------------------------------------------------------------
// bf16x3 GEMM via mma.sync:  C[128,128] tile of A[M,K] @ B[N,K]^T
//   A tensor = [2*aHalf, K] bf16 (hi rows then lo rows); same for B.
// EPI: 0 = sigmoid -> out   1 = out = W0 - lr*acc   2 = out + z*B*D = acc
// ---------------------------------------------------------------------------
template <int EPI>
__global__ __launch_bounds__(256, 1)
void gemm_mma(const __nv_bfloat16* __restrict__ Ahl, int lda, int aHalf,
              const __nv_bfloat16* __restrict__ Bhl, int ldb, int bHalf,
              int niter,
              const float* __restrict__ W0, const float* __restrict__ lr_p,
              float* __restrict__ out, int ldo)
{
    extern __shared__ char smem[];
    const uint32_t sb = smem_u32(smem);
    const int tid  = threadIdx.x;
    const int wid  = tid >> 5;
    const int lane = tid & 31;
    const int wm   = wid & 3;       // 4-way M split (32 rows each)
    const int wn   = wid >> 2;      // 2-way N split (64 cols each)
    const int m0   = blockIdx.y * CTA_M;
    const int n0   = blockIdx.x * CTA_N;
    const int k0g  = (EPI == 2) ? blockIdx.z * niter * CTA_K : 0;

    // cp.async staging map: 2048 16B chunks / stage, 8 per thread
    // chunk c: buf = c>>9 (0=Ahi,1=Alo,2=Bhi,3=Blo), row = (c&511)>>2, seg = c&3
    auto load_stage = [&](int stage, int it) {
        const uint32_t stg = sb + stage * STAGE_BYTES;
        const int kel = k0g + it * CTA_K;
#pragma unroll
        for (int i = 0; i < 8; i++) {
            const int c   = tid + i * 256;
            const int buf = c >> 9;
            const int cc  = c & 511;
            const int row = cc >> 2;
            const int seg = cc & 3;
            const __nv_bfloat16* src;
            if      (buf == 0) src = Ahl + (size_t)(m0 + row) * lda + kel + seg * 8;
            else if (buf == 1) src = Ahl + (size_t)(aHalf + m0 + row) * lda + kel + seg * 8;
            else if (buf == 2) src = Bhl + (size_t)(n0 + row) * ldb + kel + seg * 8;
            else               src = Bhl + (size_t)(bHalf + n0 + row) * ldb + kel + seg * 8;
            cp16(stg + buf * BUF_BYTES + row * ROW_PITCH + seg * 16, src);
        }
        cp_commit();
    };

    float acc[2][8][4];
#pragma unroll
    for (int i = 0; i < 2; i++)
#pragma unroll
        for (int j = 0; j < 8; j++)
#pragma unroll
            for (int v = 0; v < 4; v++) acc[i][j][v] = 0.0f;

    // ldmatrix lane decomposition
    const int rl = lane & 7;             // row within 8x8 tile
    const int hm = (lane >> 3) & 1;      // +8 row group
    const int kh = (lane >> 4) & 1;      // +8 k group (16B)

    // Prologue: stages 0, 1
    load_stage(0, 0);
    load_stage(1, 1);

    for (int it = 0; it < niter; it++) {
        if (it == niter - 1) cp_wait<0>(); else cp_wait<1>();
        __syncthreads();
        if (it + STAGES - 1 < niter)
            load_stage((it + STAGES - 1) % STAGES, it + STAGES - 1);

        const uint32_t stg = sb + (it % STAGES) * STAGE_BYTES;
#pragma unroll
        for (int ks = 0; ks < 2; ks++) {
            const int koff = ks * 32;    // 16 bf16 = 32 bytes
            uint32_t ah[2][4], al[2][4];
#pragma unroll
            for (int i = 0; i < 2; i++) {
                const int r = wm * 32 + i * 16 + hm * 8 + rl;
                const uint32_t a = stg + r * ROW_PITCH + koff + kh * 16;
                ldsm4(ah[i], a);
                ldsm4(al[i], a + BUF_BYTES);
            }
            uint32_t bh[4][4], bl[4][4];
#pragma unroll
            for (int q = 0; q < 4; q++) {
                const int r = wn * 64 + q * 16 + hm * 8 + rl;
                const uint32_t a = stg + 2 * BUF_BYTES + r * ROW_PITCH + koff + kh * 16;
                ldsm4(bh[q], a);
                ldsm4(bl[q], a + BUF_BYTES);
            }
#pragma unroll
            for (int i = 0; i < 2; i++)
#pragma unroll
                for (int q = 0; q < 4; q++)
#pragma unroll
                    for (int h = 0; h < 2; h++) {
                        const int j = 2 * q + h;
                        mma16816(acc[i][j], ah[i], bh[q][h], bh[q][h + 2]);
                        mma16816(acc[i][j], ah[i], bl[q][h], bl[q][h + 2]);
                        mma16816(acc[i][j], al[i], bh[q][h], bh[q][h + 2]);
                    }
        }
        __syncthreads();
    }

    // Epilogue
    const int t4 = lane >> 2;
    const int t2 = (lane & 3) * 2;
    float lrv = 0.0f;
    if (EPI == 1) lrv = __ldg(lr_p);
    float* optr = out;
    if (EPI == 2) optr = out + (size_t)blockIdx.z * ((size_t)B_DIM * D_DIM);

#pragma unroll
    for (int i = 0; i < 2; i++) {
        const int row = m0 + wm * 32 + i * 16 + t4;
#pragma unroll
        for (int j = 0; j < 8; j++) {
            const int col = n0 + wn * 64 + j * 8 + t2;
            float v0 = acc[i][j][0], v1 = acc[i][j][1];
            float v2 = acc[i][j][2], v3 = acc[i][j][3];
            if (EPI == 0) {
                v0 = 1.0f / (1.0f + __expf(-v0));
                v1 = 1.0f / (1.0f + __expf(-v1));
                v2 = 1.0f / (1.0f + __expf(-v2));
                v3 = 1.0f / (1.0f + __expf(-v3));
            } else if (EPI == 1) {
                float2 wa = *reinterpret_cast<const float2*>(&W0[(size_t)row * ldo + col]);
                float2 wb = *reinterpret_cast<const float2*>(&W0[(size_t)(row + 8) * ldo + col]);
                v0 = wa.x - lrv * v0; v1 = wa.y - lrv * v1;
                v2 = wb.x - lrv * v2; v3 = wb.y - lrv * v3;
            }
            *reinterpret_cast<float2*>(&optr[(size_t)row * ldo + col]) = make_float2(v0, v1);
            *reinterpret_cast<float2*>(&optr[(size_t)(row + 8) * ldo + col]) = make_float2(v2, v3);
        }
    }
}

// ---------------------------------------------------------------------------
// Convert fp32 [R,C] -> hl [2R,C] bf16 (hi rows, lo rows) and hlT [2C,R] bf16.
// ---------------------------------------------------------------------------
__global__ __launch_bounds__(256)
void k_conv_pair(const float* __restrict__ src, __nv_bfloat16* __restrict__ hl,
                 __nv_bfloat16* __restrict__ hlT, int R, int C)
{
    __shared__ float t[32][65];
    const int bx = blockIdx.x * 64;   // cols
    const int by = blockIdx.y * 32;   // rows
    const int tx = threadIdx.x, ty = threadIdx.y;

#pragma unroll
    for (int dy = 0; dy < 4; dy++) {
        int row = ty + 8 * dy;
        float2 v = *reinterpret_cast<const float2*>(&src[(size_t)(by + row) * C + bx + 2 * tx]);
        t[row][2 * tx] = v.x; t[row][2 * tx + 1] = v.y;
    }
    __syncthreads();

#pragma unroll
    for (int dy = 0; dy < 4; dy++) {
        int row = ty + 8 * dy;
        float f0 = t[row][2 * tx], f1 = t[row][2 * tx + 1];
        __nv_bfloat16 h0 = __float2bfloat16(f0), h1 = __float2bfloat16(f1);
        __nv_bfloat16 l0 = __float2bfloat16(f0 - __bfloat162float(h0));
        __nv_bfloat16 l1 = __float2bfloat16(f1 - __bfloat162float(h1));
        __nv_bfloat162 hp; hp.x = h0; hp.y = h1;
        __nv_bfloat162 lp; lp.x = l0; lp.y = l1;
        *reinterpret_cast<__nv_bfloat162*>(&hl[(size_t)(by + row) * C + bx + 2 * tx]) = hp;
        *reinterpret_cast<__nv_bfloat162*>(&hl[((size_t)R + by + row) * C + bx + 2 * tx]) = lp;
    }
#pragma unroll
    for (int dc = 0; dc < 8; dc++) {
        int c = ty + 8 * dc;
        float f = t[tx][c];
        __nv_bfloat16 h = __float2bfloat16(f);
        __nv_bfloat16 l = __float2bfloat16(f - __bfloat162float(h));
        hlT[((size_t)bx + c) * R + by + tx] = h;
        hlT[((size_t)C + bx + c) * R + by + tx] = l;
    }
}

// ---------------------------------------------------------------------------
// Scatter: g[label_cols[i], label_rows[i]] -= 1 (const add: order-invariant)
// ---------------------------------------------------------------------------
__global__ void k_scatter(const int* __restrict__ rows, const int* __restrict__ cols) {
    int i = blockIdx.x * blockDim.x + threadIdx.x;
    if (i < NNZ_DIM)
        atomicAdd(&g_buf[(size_t)cols[i] * B_DIM + rows[i]], -1.0f);
}

// ---------------------------------------------------------------------------
// Deterministic fixed-order split-K reduction
// ---------------------------------------------------------------------------
__global__ __launch_bounds__(256)
void k4_reduce(float* __restrict__ grad) {
    const int n = B_DIM * D_DIM;
    int i4 = blockIdx.x * blockDim.x + threadIdx.x;
    if (i4 * 4 >= n) return;
    float4 s = make_float4(0.f, 0.f, 0.f, 0.f);
#pragma unroll
    for (int z = 0; z < K3_SPLITS; z++) {
        float4 v = *reinterpret_cast<const float4*>(&part_buf[(size_t)z * n + i4 * 4]);
        s.x += v.x; s.y += v.y; s.z += v.z; s.w += v.w;
    }
    *reinterpret_cast<float4*>(&grad[i4 * 4]) = s;
}

// ---------------------------------------------------------------------------
// Launch. Output layout: [grad_input (B*D) | w_new (L*D)]
// ---------------------------------------------------------------------------
extern "C" void kernel_launch(void* const* d_in, const int* in_sizes, int n_in,
                              void* d_out, int out_size) {
    const float* embed  = nullptr;
    const float* weight = nullptr;
    const float* lr     = nullptr;
    const int*   rows   = nullptr;
    const int*   cols   = nullptr;
    for (int i = 0; i < n_in; i++) {
        int s = in_sizes[i];
        if (s == B_DIM * D_DIM)                 embed  = (const float*)d_in[i];
        else if (s == 1)                        lr     = (const float*)d_in[i];
        else if (s == NNZ_DIM) {
            if (!rows) rows = (const int*)d_in[i];
            else       cols = (const int*)d_in[i];
        } else                                  weight = (const float*)d_in[i];
    }

    float* out  = (float*)d_out;
    float* grad = out;                                   // [B, D]
    float* wout = out + (size_t)B_DIM * D_DIM;           // [L, D]

    void *gp, *pWhl, *pWThl, *pghl, *pgThl, *pEhl, *pEThl, *pp;
    cudaGetSymbolAddress(&gp,    g_buf);
    cudaGetSymbolAddress(&pWhl,  Whl);
    cudaGetSymbolAddress(&pWThl, WThl);
    cudaGetSymbolAddress(&pghl,  ghl);
    cudaGetSymbolAddress(&pgThl, gThl);
    cudaGetSymbolAddress(&pEhl,  Ehl);
    cudaGetSymbolAddress(&pEThl, EThl);
    cudaGetSymbolAddress(&pp,    part_buf);

    cudaFuncSetAttribute(gemm_mma<0>, cudaFuncAttributeMaxDynamicSharedMemorySize, GEMM_SMEM);
    cudaFuncSetAttribute(gemm_mma<1>, cudaFuncAttributeMaxDynamicSharedMemorySize, GEMM_SMEM);
    cudaFuncSetAttribute(gemm_mma<2>, cudaFuncAttributeMaxDynamicSharedMemorySize, GEMM_SMEM);

    // Convert E and W to bf16 hi/lo (+ transposed copies)
    k_conv_pair<<<dim3(D_DIM / 64, B_DIM / 32), dim3(32, 8)>>>(
        embed, (__nv_bfloat16*)pEhl, (__nv_bfloat16*)pEThl, B_DIM, D_DIM);
    k_conv_pair<<<dim3(D_DIM / 64, L_DIM / 32), dim3(32, 8)>>>(
        weight, (__nv_bfloat16*)pWhl, (__nv_bfloat16*)pWThl, L_DIM, D_DIM);

    // K1: g = sigmoid(W @ E^T)  [L,B], K = 768 -> 24 iters
    gemm_mma<0><<<dim3(B_DIM / CTA_N, L_DIM / CTA_M, 1), 256, GEMM_SMEM>>>(
        (const __nv_bfloat16*)pWhl, D_DIM, L_DIM,
        (const __nv_bfloat16*)pEhl, D_DIM, B_DIM,
        D_DIM / CTA_K, nullptr, nullptr, (float*)gp, B_DIM);

    // scatter -1 at positives
    k_scatter<<<NNZ_DIM / 256, 256>>>(rows, cols);

    // Convert g to bf16 hi/lo (+ transposed)
    k_conv_pair<<<dim3(B_DIM / 64, L_DIM / 32), dim3(32, 8)>>>(
        (const float*)gp, (__nv_bfloat16*)pghl, (__nv_bfloat16*)pgThl, L_DIM, B_DIM);

    // K2: Wout = W - lr*(g @ E)  [L,D], K = 512 -> 16 iters
    gemm_mma<1><<<dim3(D_DIM / CTA_N, L_DIM / CTA_M, 1), 256, GEMM_SMEM>>>(
        (const __nv_bfloat16*)pghl, B_DIM, L_DIM,
        (const __nv_bfloat16*)pEThl, B_DIM, D_DIM,
        B_DIM / CTA_K, weight, lr, wout, D_DIM);

    // K3: part[z] = (g^T @ W) chunk  [B,D], K-chunk = 4096 -> 128 iters, 32 slices
    gemm_mma<2><<<dim3(D_DIM / CTA_N, B_DIM / CTA_M, K3_SPLITS), 256, GEMM_SMEM>>>(
        (const __nv_bfloat16*)pgThl, L_DIM, B_DIM,
        (const __nv_bfloat16*)pWThl, L_DIM, D_DIM,
        K3_CHUNK / CTA_K, nullptr, nullptr, (float*)pp, D_DIM);

    // Deterministic fixed-order reduce
    k4_reduce<<<(B_DIM * D_DIM / 4 + 255) / 256, 256>>>(grad);
}